// round 6
// baseline (speedup 1.0000x reference)
#include <cuda_runtime.h>
#include <cuda_bf16.h>
#include <math.h>

#define FULL_MASK 0xffffffffu
#define AP 24   // smem row pitch in bf16 elems (48B) -> conflict-free ldmatrix

// ---------------- scratch (__device__ globals; no runtime allocation) -------
__device__ __align__(16) __nv_bfloat16 g_q[32u*1024u*32u];  // [bf][t][c], pre-scaled by 1/sqrt(hd)
__device__ __align__(16) __nv_bfloat16 g_k[8u*1024u*32u];   // [b][s][c]
__device__ __align__(16) __nv_bfloat16 g_v[8u*1024u*32u];   // [b][s][c]
__device__ __align__(16) float          g_y[32u*1024u*32u]; // attention output, fp32

__device__ __forceinline__ float gelu_exact(float v) {
    return 0.5f * v * (1.f + erff(v * 0.70710678118654752440f));
}

// ======================= TCL: causal conv(k=3) + GELU + proj =================
// x: [N,1024,32] fp32 ; wconv [64,32,3]; wproj [32,64]; out bf16 (which selects q/k/v)
__global__ void __launch_bounds__(64) tcl_kernel(
    const float* __restrict__ x,
    const float* __restrict__ wconv, const float* __restrict__ bconv,
    const float* __restrict__ wproj, const float* __restrict__ bproj,
    int which, float scale)
{
    __shared__ alignas(16) float sW[32*3*64];   // [ci][k][j] (j contiguous)
    __shared__ alignas(16) float sWp[64*32];    // [j][c]     (c contiguous)
    __shared__ float sB[64];
    __shared__ float sBp[32];
    __shared__ float sx[66][33];                // pitch 33 -> conflict-free column reads
    const int T = 1024;
    int n = blockIdx.y, t0 = blockIdx.x * 64, tid = threadIdx.x;

    for (int i = tid; i < 6144; i += 64) {
        int j = i / 96, r = i - j * 96, ci = r / 3, kk = r - ci * 3;
        sW[(ci*3 + kk)*64 + j] = wconv[i];
    }
    for (int i = tid; i < 2048; i += 64) {
        int c = i >> 6, j = i & 63;
        sWp[j*32 + c] = wproj[i];
    }
    sB[tid] = bconv[tid];
    if (tid < 32) sBp[tid] = bproj[tid];
    for (int i = tid; i < 66*32; i += 64) {
        int r = i >> 5, c = i & 31;
        int t = t0 - 2 + r;
        sx[r][c] = (t >= 0) ? x[((size_t)n*T + t)*32 + c] : 0.f;
    }
    __syncthreads();

    float acc[64];
    #pragma unroll
    for (int j = 0; j < 64; j++) acc[j] = sB[j];

    #pragma unroll 1
    for (int ci = 0; ci < 32; ci++) {
        float x0 = sx[tid + 0][ci];
        float x1 = sx[tid + 1][ci];
        float x2 = sx[tid + 2][ci];
        const float4* w0 = (const float4*)&sW[(ci*3 + 0)*64];
        const float4* w1 = (const float4*)&sW[(ci*3 + 1)*64];
        const float4* w2 = (const float4*)&sW[(ci*3 + 2)*64];
        #pragma unroll
        for (int j4 = 0; j4 < 16; j4++) {
            float4 a = w0[j4], b = w1[j4], c = w2[j4];
            acc[4*j4+0] += a.x*x0 + b.x*x1 + c.x*x2;
            acc[4*j4+1] += a.y*x0 + b.y*x1 + c.y*x2;
            acc[4*j4+2] += a.z*x0 + b.z*x1 + c.z*x2;
            acc[4*j4+3] += a.w*x0 + b.w*x1 + c.w*x2;
        }
    }
    #pragma unroll
    for (int j = 0; j < 64; j++) acc[j] = gelu_exact(acc[j]);

    float oacc[32];
    #pragma unroll
    for (int c = 0; c < 32; c++) oacc[c] = sBp[c];
    #pragma unroll 1
    for (int j = 0; j < 64; j++) {
        float hv = acc[j];
        const float4* wp = (const float4*)&sWp[j*32];
        #pragma unroll
        for (int c4 = 0; c4 < 8; c4++) {
            float4 wv = wp[c4];
            oacc[4*c4+0] += wv.x * hv;
            oacc[4*c4+1] += wv.y * hv;
            oacc[4*c4+2] += wv.z * hv;
            oacc[4*c4+3] += wv.w * hv;
        }
    }
    __nv_bfloat16* out = (which == 0) ? g_q : (which == 1) ? g_k : g_v;
    size_t base = ((size_t)n*T + t0 + tid) * 32;
    #pragma unroll
    for (int c = 0; c < 32; c += 2) {
        __nv_bfloat162 p = __floats2bfloat162_rn(oacc[c]*scale, oacc[c+1]*scale);
        *(__nv_bfloat162*)(&out[base + c]) = p;
    }
}

// ======================= flash attention (warp-level HMMA) ===================
__device__ __forceinline__ unsigned sm_u32(const void* p) {
    return (unsigned)__cvta_generic_to_shared(p);
}
__device__ __forceinline__ void ldm_x4(unsigned &r0, unsigned &r1, unsigned &r2, unsigned &r3, unsigned a) {
    asm volatile("ldmatrix.sync.aligned.m8n8.x4.shared.b16 {%0,%1,%2,%3}, [%4];"
        : "=r"(r0), "=r"(r1), "=r"(r2), "=r"(r3) : "r"(a));
}
__device__ __forceinline__ void ldm_x4_t(unsigned &r0, unsigned &r1, unsigned &r2, unsigned &r3, unsigned a) {
    asm volatile("ldmatrix.sync.aligned.m8n8.x4.trans.shared.b16 {%0,%1,%2,%3}, [%4];"
        : "=r"(r0), "=r"(r1), "=r"(r2), "=r"(r3) : "r"(a));
}
__device__ __forceinline__ void mma16816(float* d,
        unsigned a0, unsigned a1, unsigned a2, unsigned a3,
        unsigned b0, unsigned b1, const float* c) {
    asm volatile("mma.sync.aligned.m16n8k16.row.col.f32.bf16.bf16.f32 "
        "{%0,%1,%2,%3}, {%4,%5,%6,%7}, {%8,%9}, {%10,%11,%12,%13};"
        : "=f"(d[0]), "=f"(d[1]), "=f"(d[2]), "=f"(d[3])
        : "r"(a0), "r"(a1), "r"(a2), "r"(a3), "r"(b0), "r"(b1),
          "f"(c[0]), "f"(c[1]), "f"(c[2]), "f"(c[3]));
}
__device__ __forceinline__ unsigned packbf2(float lo, float hi) {
    __nv_bfloat162 t = __floats2bfloat162_rn(lo, hi);
    return *(unsigned*)&t;
}

// grid: (T/64, nh=2, B*F=32); block 128 (4 warps, 16 q-rows each)
__global__ void __launch_bounds__(128) attn_kernel()
{
    __shared__ alignas(16) __nv_bfloat16 Qs[64*AP];
    __shared__ alignas(16) __nv_bfloat16 Ks[64*AP];
    __shared__ alignas(16) __nv_bfloat16 Vs[64*AP];
    int bf = blockIdx.z;
    int b  = bf >> 2;
    int h  = blockIdx.y;
    int t0 = blockIdx.x * 64;
    int tid = threadIdx.x, lane = tid & 31, w = tid >> 5;
    int ldrow = tid >> 1, ldhalf = tid & 1;

    // stage Q tile (64 rows x 16 cols of this head)
    *(uint4*)&Qs[ldrow*AP + ldhalf*8] =
        *(const uint4*)&g_q[((size_t)bf*1024 + t0 + ldrow)*32 + h*16 + ldhalf*8];
    __syncthreads();
    unsigned qa0, qa1, qa2, qa3;
    ldm_x4(qa0, qa1, qa2, qa3, sm_u32(&Qs[(w*16 + (lane & 15))*AP + (lane >> 4)*8]));

    float m0 = -1e30f, m1 = -1e30f, l0 = 0.f, l1 = 0.f;
    float o[2][4];
    #pragma unroll
    for (int n = 0; n < 2; n++)
        #pragma unroll
        for (int i = 0; i < 4; i++) o[n][i] = 0.f;

    size_t kvbase = (size_t)b*1024*32 + h*16 + ldhalf*8;

    for (int s0 = 0; s0 < 1024; s0 += 64) {
        __syncthreads();
        *(uint4*)&Ks[ldrow*AP + ldhalf*8] = *(const uint4*)&g_k[kvbase + (size_t)(s0 + ldrow)*32];
        *(uint4*)&Vs[ldrow*AP + ldhalf*8] = *(const uint4*)&g_v[kvbase + (size_t)(s0 + ldrow)*32];
        __syncthreads();

        // S = Q K^T  (scale pre-folded into q)
        float sc[8][4];
        #pragma unroll
        for (int nb = 0; nb < 4; nb++) {
            unsigned r0, r1, r2, r3;
            ldm_x4(r0, r1, r2, r3, sm_u32(&Ks[(nb*16 + (lane & 15))*AP + (lane >> 4)*8]));
            float z[4] = {0.f, 0.f, 0.f, 0.f};
            mma16816(sc[2*nb + 0], qa0, qa1, qa2, qa3, r0, r2, z);
            mma16816(sc[2*nb + 1], qa0, qa1, qa2, qa3, r1, r3, z);
        }
        // online softmax; regs {0,1} -> row lane/4, {2,3} -> row lane/4 + 8
        float nm0 = m0, nm1 = m1;
        #pragma unroll
        for (int t = 0; t < 8; t++) {
            nm0 = fmaxf(nm0, fmaxf(sc[t][0], sc[t][1]));
            nm1 = fmaxf(nm1, fmaxf(sc[t][2], sc[t][3]));
        }
        nm0 = fmaxf(nm0, __shfl_xor_sync(FULL_MASK, nm0, 1));
        nm0 = fmaxf(nm0, __shfl_xor_sync(FULL_MASK, nm0, 2));
        nm1 = fmaxf(nm1, __shfl_xor_sync(FULL_MASK, nm1, 1));
        nm1 = fmaxf(nm1, __shfl_xor_sync(FULL_MASK, nm1, 2));
        float a0 = __expf(m0 - nm0), a1 = __expf(m1 - nm1);
        float rs0 = 0.f, rs1 = 0.f;
        #pragma unroll
        for (int t = 0; t < 8; t++) {
            sc[t][0] = __expf(sc[t][0] - nm0);
            sc[t][1] = __expf(sc[t][1] - nm0);
            sc[t][2] = __expf(sc[t][2] - nm1);
            sc[t][3] = __expf(sc[t][3] - nm1);
            rs0 += sc[t][0] + sc[t][1];
            rs1 += sc[t][2] + sc[t][3];
        }
        rs0 += __shfl_xor_sync(FULL_MASK, rs0, 1);
        rs0 += __shfl_xor_sync(FULL_MASK, rs0, 2);
        rs1 += __shfl_xor_sync(FULL_MASK, rs1, 1);
        rs1 += __shfl_xor_sync(FULL_MASK, rs1, 2);
        l0 = l0*a0 + rs0; l1 = l1*a1 + rs1;
        m0 = nm0; m1 = nm1;
        #pragma unroll
        for (int n = 0; n < 2; n++) {
            o[n][0] *= a0; o[n][1] *= a0; o[n][2] *= a1; o[n][3] *= a1;
        }
        // O += P V  (C-frag -> A-frag repack; V via ldmatrix.trans)
        #pragma unroll
        for (int kb = 0; kb < 4; kb++) {
            unsigned pa0 = packbf2(sc[2*kb][0],   sc[2*kb][1]);
            unsigned pa1 = packbf2(sc[2*kb][2],   sc[2*kb][3]);
            unsigned pa2 = packbf2(sc[2*kb+1][0], sc[2*kb+1][1]);
            unsigned pa3 = packbf2(sc[2*kb+1][2], sc[2*kb+1][3]);
            unsigned v0, v1, v2, v3;
            ldm_x4_t(v0, v1, v2, v3,
                sm_u32(&Vs[(kb*16 + ((lane >> 3) & 1)*8 + (lane & 7))*AP + (lane >> 4)*8]));
            mma16816(o[0], pa0, pa1, pa2, pa3, v0, v1, o[0]);
            mma16816(o[1], pa0, pa1, pa2, pa3, v2, v3, o[1]);
        }
    }
    float inv0 = 1.f / l0, inv1 = 1.f / l1;
    int g = lane >> 2, c2 = (lane & 3) * 2;
    size_t rbase = ((size_t)bf*1024 + t0 + w*16 + g)*32 + h*16;
    #pragma unroll
    for (int n = 0; n < 2; n++) {
        g_y[rbase + n*8 + c2]              = o[n][0]*inv0;
        g_y[rbase + n*8 + c2 + 1]          = o[n][1]*inv0;
        g_y[rbase + 8*32 + n*8 + c2]       = o[n][2]*inv1;
        g_y[rbase + 8*32 + n*8 + c2 + 1]   = o[n][3]*inv1;
    }
}

// ============== epilogue: out = x + y@Wc^T; h=LN(out); out += MLP(h) ========
__global__ void __launch_bounds__(256) epilogue_kernel(
    const float* __restrict__ causal,
    const float* __restrict__ wc,   // [32,32] row-major: wc[c][j]
    const float* __restrict__ lnw,  // [32]
    const float* __restrict__ wfc,  // [32,32]
    const float* __restrict__ wmp,  // [32,32]
    float* __restrict__ out)
{
    __shared__ float sWc[32*32];   // [j][c]
    __shared__ float sWfc[32*32];  // [j][c]
    __shared__ float sWmp[32*32];  // [j][c]
    __shared__ float sLn[32];
    int tid = threadIdx.x, lane = tid & 31, w = tid >> 5;
    for (int i = tid; i < 1024; i += 256) {
        int c = i >> 5, j = i & 31;
        sWc [j*32 + c] = wc[i];
        sWfc[j*32 + c] = wfc[i];
        sWmp[j*32 + c] = wmp[i];
    }
    if (tid < 32) sLn[tid] = lnw[tid];
    __syncthreads();

    const int NROWS = 32 * 1024;
    for (int row = blockIdx.x * 8 + w; row < NROWS; row += gridDim.x * 8) {
        float yv = g_y[(size_t)row*32 + lane];
        float cp = 0.f;
        #pragma unroll
        for (int j = 0; j < 32; j++)
            cp += sWc[j*32 + lane] * __shfl_sync(FULL_MASK, yv, j);
        float ov = causal[(size_t)row*32 + lane] + cp;

        float mu = ov;
        #pragma unroll
        for (int m = 16; m >= 1; m >>= 1) mu += __shfl_xor_sync(FULL_MASK, mu, m);
        mu *= (1.f/32.f);
        float d = ov - mu;
        float var = d*d;
        #pragma unroll
        for (int m = 16; m >= 1; m >>= 1) var += __shfl_xor_sync(FULL_MASK, var, m);
        var *= (1.f/32.f);
        float hn = d * rsqrtf(var + 1e-5f) * sLn[lane];

        float fcv = 0.f;
        #pragma unroll
        for (int j = 0; j < 32; j++)
            fcv += sWfc[j*32 + lane] * __shfl_sync(FULL_MASK, hn, j);
        fcv = gelu_exact(fcv);

        float mp = 0.f;
        #pragma unroll
        for (int j = 0; j < 32; j++)
            mp += sWmp[j*32 + lane] * __shfl_sync(FULL_MASK, fcv, j);

        out[(size_t)row*32 + lane] = ov + mp;
    }
}

// ============================= launch ========================================
extern "C" void kernel_launch(void* const* d_in, const int* in_sizes, int n_in,
                              void* d_out, int out_size) {
    (void)in_sizes; (void)n_in; (void)out_size;
    const float* causal = (const float*)d_in[0];
    const float* past   = (const float*)d_in[1];

    // q TCL (scale = 1/sqrt(hd) = 0.25 folded in)
    tcl_kernel<<<dim3(16, 32), 64>>>(causal,
        (const float*)d_in[2], (const float*)d_in[3],
        (const float*)d_in[4], (const float*)d_in[5], 0, 0.25f);
    // k TCL
    tcl_kernel<<<dim3(16, 8), 64>>>(past,
        (const float*)d_in[6], (const float*)d_in[7],
        (const float*)d_in[8], (const float*)d_in[9], 1, 1.0f);
    // v TCL
    tcl_kernel<<<dim3(16, 8), 64>>>(past,
        (const float*)d_in[10], (const float*)d_in[11],
        (const float*)d_in[12], (const float*)d_in[13], 2, 1.0f);

    attn_kernel<<<dim3(16, 2, 32), 128>>>();

    epilogue_kernel<<<1024, 256>>>(causal,
        (const float*)d_in[14], (const float*)d_in[15],
        (const float*)d_in[16], (const float*)d_in[17],
        (float*)d_out);
}